// round 6
// baseline (speedup 1.0000x reference)
#include <cuda_runtime.h>
#include <math.h>
#include <stdint.h>

#define BB 16
#define NNX 512
#define CCX 384
#define HHX 6
#define HDX 64
#define FFD 1152
#define BHX (BB*HHX)        // 96
#define MTOK (BB*NNX)       // 8192
#define OUT_ATTN_OFF ((size_t)MTOK*CCX)   // 3145728

// ---------------- device scratch (no dynamic allocation allowed) ----------------
__device__ float g_x[MTOK*CCX];
__device__ float g_q[BHX*NNX*HDX];
__device__ float g_k[BHX*NNX*HDX];
__device__ float g_v[BHX*NNX*HDX];
__device__ float g_qgr[BHX*NNX*HDX];
__device__ float g_kgr[BHX*NNX*HDX];
__device__ float g_qn4[BHX*NNX];
__device__ float g_kn4[BHX*NNX];
__device__ float g_qk[BHX*NNX*NNX];
__device__ float g_dd[BHX*NNX*NNX];
__device__ float g_attnv[MTOK*CCX];
__device__ float g_src1[MTOK*CCX];
__device__ float g_hff[MTOK*FFD];

// ======================= LayerNorm (row of 384, 128 threads) =======================
__global__ void ln_kernel(const float* __restrict__ in, const float* __restrict__ w,
                          const float* __restrict__ b, float* __restrict__ out)
{
    int row = blockIdx.x;
    int t = threadIdx.x;
    const float* p = in + (size_t)row * CCX;
    float v0 = p[t], v1 = p[t + 128], v2 = p[t + 256];
    __shared__ float sh[4];
    float s = v0 + v1 + v2;
#pragma unroll
    for (int o = 16; o; o >>= 1) s += __shfl_xor_sync(0xffffffffu, s, o);
    if ((t & 31) == 0) sh[t >> 5] = s;
    __syncthreads();
    float mu = (sh[0] + sh[1] + sh[2] + sh[3]) * (1.0f / CCX);
    __syncthreads();
    float d0 = v0 - mu, d1 = v1 - mu, d2 = v2 - mu;
    float s2 = d0 * d0 + d1 * d1 + d2 * d2;
#pragma unroll
    for (int o = 16; o; o >>= 1) s2 += __shfl_xor_sync(0xffffffffu, s2, o);
    if ((t & 31) == 0) sh[t >> 5] = s2;
    __syncthreads();
    float var = (sh[0] + sh[1] + sh[2] + sh[3]) * (1.0f / CCX);
    float r = rsqrtf(var + 1e-5f);
    float* q = out + (size_t)row * CCX;
    q[t]       = d0 * r * w[t]       + b[t];
    q[t + 128] = d1 * r * w[t + 128] + b[t + 128];
    q[t + 256] = d2 * r * w[t + 256] + b[t + 256];
}

// ======================= generic SGEMM: C[M,L] = A[M,K] @ W[L,K]^T + bias =======================
#define EPI_NONE 0
#define EPI_QKV  1
#define EPI_GELU 2
#define EPI_RESID 3

template<int EPI>
__global__ __launch_bounds__(256)
void sgemm_abt(const float* __restrict__ A, const float* __restrict__ W,
               const float* __restrict__ bias, const float* __restrict__ resid,
               float* __restrict__ C, int M, int L, int K)
{
    __shared__ float As[16 * 132];
    __shared__ float Ws[16 * 68];
    int m0 = blockIdx.y * 128;
    int l0 = blockIdx.x * 64;
    int t = threadIdx.x;
    int tm = t >> 4, tn = t & 15;
    float acc[8][4];
#pragma unroll
    for (int i = 0; i < 8; i++)
#pragma unroll
        for (int j = 0; j < 4; j++) acc[i][j] = 0.f;

    for (int kt = 0; kt < K; kt += 16) {
#pragma unroll
        for (int u = 0; u < 2; u++) {
            int p = t + u * 256;
            int r = p >> 2, cg = p & 3;
            float4 av = *(const float4*)(A + (size_t)(m0 + r) * K + kt + cg * 4);
            As[(cg * 4 + 0) * 132 + r] = av.x;
            As[(cg * 4 + 1) * 132 + r] = av.y;
            As[(cg * 4 + 2) * 132 + r] = av.z;
            As[(cg * 4 + 3) * 132 + r] = av.w;
        }
        {
            int r = t >> 2, cg = t & 3;
            float4 wv = *(const float4*)(W + (size_t)(l0 + r) * K + kt + cg * 4);
            Ws[(cg * 4 + 0) * 68 + r] = wv.x;
            Ws[(cg * 4 + 1) * 68 + r] = wv.y;
            Ws[(cg * 4 + 2) * 68 + r] = wv.z;
            Ws[(cg * 4 + 3) * 68 + r] = wv.w;
        }
        __syncthreads();
#pragma unroll
        for (int k = 0; k < 16; k++) {
            float a[8], bv[4];
#pragma unroll
            for (int i = 0; i < 8; i++) a[i] = As[k * 132 + tm * 8 + i];
#pragma unroll
            for (int j = 0; j < 4; j++) bv[j] = Ws[k * 68 + tn * 4 + j];
#pragma unroll
            for (int i = 0; i < 8; i++)
#pragma unroll
                for (int j = 0; j < 4; j++) acc[i][j] += a[i] * bv[j];
        }
        __syncthreads();
    }

#pragma unroll
    for (int i = 0; i < 8; i++) {
#pragma unroll
        for (int j = 0; j < 4; j++) {
            int row = m0 + tm * 8 + i;
            int col = l0 + tn * 4 + j;
            float val = acc[i][j] + bias[col];
            if (EPI == EPI_NONE) {
                C[(size_t)row * L + col] = val;
            } else if (EPI == EPI_GELU) {
                C[(size_t)row * L + col] = 0.5f * val * (1.0f + erff(val * 0.70710678118654752f));
            } else if (EPI == EPI_RESID) {
                C[(size_t)row * L + col] = val + resid[(size_t)row * L + col];
            } else { // QKV scatter
                int three = col / 384;
                int rem = col - three * 384;
                int h = rem >> 6, d = rem & 63;
                int b = row >> 9, n = row & 511;
                float* dst = (three == 0) ? g_q : ((three == 1) ? g_k : g_v);
                dst[((size_t)(b * 6 + h) * 512 + n) * 64 + d] = val;
            }
        }
    }
}

// ======================= per-row squared-norms^2 =======================
__global__ void norms_kernel()
{
    int idx = blockIdx.x * 256 + threadIdx.x;
    if (idx >= BHX * NNX) return;
    const float* pq = g_q + (size_t)idx * 64;
    const float* pk = g_k + (size_t)idx * 64;
    float sq = 0.f, sk = 0.f;
#pragma unroll
    for (int d = 0; d < 64; d++) { sq += pq[d] * pq[d]; sk += pk[d] * pk[d]; }
    g_qn4[idx] = sq * sq;
    g_kn4[idx] = sk * sk;
}

// ======================= register-resident Householder QR (512x64, reduced Q) =======================
// One block per matrix, 512 threads. Warp w owns columns 4w..4w+3;
// lane l owns rows 16l..16l+15. Each thread keeps a 4x16 register tile.
// __launch_bounds__(512, 1): allow 128 regs/thread so the tile never spills.
// LAPACK sgeqr2 + sorg2r conventions (beta = -copysign(|x|, alpha)).
__global__ __launch_bounds__(512, 1)
void qr_kernel2(const float* __restrict__ X0, float* __restrict__ Q0,
                const float* __restrict__ X1, float* __restrict__ Q1)
{
    int bh = blockIdx.x;
    const float* src = (bh < BHX) ? (X0 + (size_t)bh * 512 * 64)
                                  : (X1 + (size_t)(bh - BHX) * 512 * 64);
    float* dst = (bh < BHX) ? (Q0 + (size_t)bh * 512 * 64)
                            : (Q1 + (size_t)(bh - BHX) * 512 * 64);
    int t = threadIdx.x;
    int w = t >> 5, l = t & 31;
    __shared__ float vsh[512];
    __shared__ float tauv[64];

    float a[4][16];
#pragma unroll
    for (int r = 0; r < 16; r++) {
        float4 v4 = *(const float4*)(src + (size_t)(16 * l + r) * 64 + 4 * w);
        a[0][r] = v4.x; a[1][r] = v4.y; a[2][r] = v4.z; a[3][r] = v4.w;
    }

    // ---------------- geqrf ----------------
    for (int j = 0; j < 64; j++) {
        int jw = j >> 2, jc = j & 3;
        if (w == jw) {
            int lj = j >> 4, rj = j & 15;
            float n2 = 0.f;
#pragma unroll
            for (int r = 0; r < 16; r++) {
                int i = 16 * l + r;
                float x = a[jc][r];
                n2 += (i > j) ? x * x : 0.f;
            }
#pragma unroll
            for (int o = 16; o; o >>= 1) n2 += __shfl_xor_sync(0xffffffffu, n2, o);
            float alpha = __shfl_sync(0xffffffffu, a[jc][rj], lj);
            float tau, scal, beta;
            if (n2 == 0.f) { tau = 0.f; scal = 0.f; beta = alpha; }
            else {
                beta = -copysignf(sqrtf(alpha * alpha + n2), alpha);
                tau  = (beta - alpha) / beta;
                scal = 1.0f / (alpha - beta);
            }
#pragma unroll
            for (int r = 0; r < 16; r++) {
                int i = 16 * l + r;
                float vv;
                if (i < j) vv = 0.f;
                else if (i == j) { vv = 1.f; a[jc][r] = beta; }
                else { vv = a[jc][r] * scal; a[jc][r] = vv; }
                vsh[i] = vv;
            }
            if (l == 0) tauv[j] = tau;
        }
        __syncthreads();
        float tau = tauv[j];
        if (tau != 0.f && (4 * w + 3) > j) {
            float vr[16];
#pragma unroll
            for (int r = 0; r < 16; r++) vr[r] = vsh[16 * l + r];
#pragma unroll
            for (int c = 0; c < 4; c++) {
                int C = 4 * w + c;
                if (C > j) {
                    float s = 0.f;
#pragma unroll
                    for (int r = 0; r < 16; r++) s += vr[r] * a[c][r];
#pragma unroll
                    for (int o = 16; o; o >>= 1) s += __shfl_xor_sync(0xffffffffu, s, o);
                    float wc = tau * s;
#pragma unroll
                    for (int r = 0; r < 16; r++) a[c][r] -= vr[r] * wc;
                }
            }
        }
        __syncthreads();
    }

    // ---------------- org2r (backward, in place) ----------------
    for (int j = 63; j >= 0; j--) {
        int jw = j >> 2, jc = j & 3;
        float tau = tauv[j];
        if (w == jw) {
#pragma unroll
            for (int r = 0; r < 16; r++) {
                int i = 16 * l + r;
                float vv;
                if (i < j) vv = 0.f;
                else if (i == j) vv = 1.f;
                else vv = a[jc][r];
                vsh[i] = vv;
            }
        }
        __syncthreads();
        if (tau != 0.f && (4 * w + 3) > j) {
            float vr[16];
#pragma unroll
            for (int r = 0; r < 16; r++) vr[r] = vsh[16 * l + r];
#pragma unroll
            for (int c = 0; c < 4; c++) {
                int C = 4 * w + c;
                if (C > j) {
                    float s = 0.f;
#pragma unroll
                    for (int r = 0; r < 16; r++) s += vr[r] * a[c][r];
#pragma unroll
                    for (int o = 16; o; o >>= 1) s += __shfl_xor_sync(0xffffffffu, s, o);
                    float wc = tau * s;
#pragma unroll
                    for (int r = 0; r < 16; r++) a[c][r] -= vr[r] * wc;
                }
            }
        }
        // owner converts column j into a Q column
        if (w == jw) {
#pragma unroll
            for (int r = 0; r < 16; r++) {
                int i = 16 * l + r;
                float val;
                if (i < j) val = 0.f;
                else if (i == j) val = 1.f - tau;
                else val = -tau * a[jc][r];
                a[jc][r] = val;
            }
        }
        __syncthreads();
    }

#pragma unroll
    for (int r = 0; r < 16; r++) {
        float4 v4 = make_float4(a[0][r], a[1][r], a[2][r], a[3][r]);
        *(float4*)(dst + (size_t)(16 * l + r) * 64 + 4 * w) = v4;
    }
}

// ======================= batched NT GEMM: C[bh][512,512] = X[bh][512,64] @ Y[bh][512,64]^T =======================
__global__ __launch_bounds__(256)
void bgemm_nt(const float* __restrict__ X, const float* __restrict__ Y, float* __restrict__ C)
{
    __shared__ float Xs[64 * 68];
    __shared__ float Ys[64 * 68];
    int bh = blockIdx.z;
    int m0 = blockIdx.y * 64, n0 = blockIdx.x * 64;
    int t = threadIdx.x, tm = t >> 4, tn = t & 15;
    const float* Xp = X + (size_t)bh * NNX * HDX;
    const float* Yp = Y + (size_t)bh * NNX * HDX;
#pragma unroll
    for (int u = 0; u < 4; u++) {
        int p = t + u * 256;
        int r = p >> 4, cg = p & 15;
        float4 xv = *(const float4*)(Xp + (size_t)(m0 + r) * 64 + cg * 4);
        Xs[(cg * 4 + 0) * 68 + r] = xv.x;
        Xs[(cg * 4 + 1) * 68 + r] = xv.y;
        Xs[(cg * 4 + 2) * 68 + r] = xv.z;
        Xs[(cg * 4 + 3) * 68 + r] = xv.w;
        float4 yv = *(const float4*)(Yp + (size_t)(n0 + r) * 64 + cg * 4);
        Ys[(cg * 4 + 0) * 68 + r] = yv.x;
        Ys[(cg * 4 + 1) * 68 + r] = yv.y;
        Ys[(cg * 4 + 2) * 68 + r] = yv.z;
        Ys[(cg * 4 + 3) * 68 + r] = yv.w;
    }
    __syncthreads();
    float acc[4][4];
#pragma unroll
    for (int i = 0; i < 4; i++)
#pragma unroll
        for (int j = 0; j < 4; j++) acc[i][j] = 0.f;
#pragma unroll 16
    for (int k = 0; k < 64; k++) {
        float a[4], b[4];
#pragma unroll
        for (int i = 0; i < 4; i++) a[i] = Xs[k * 68 + tm * 4 + i];
#pragma unroll
        for (int j = 0; j < 4; j++) b[j] = Ys[k * 68 + tn * 4 + j];
#pragma unroll
        for (int i = 0; i < 4; i++)
#pragma unroll
            for (int j = 0; j < 4; j++) acc[i][j] += a[i] * b[j];
    }
    float* Cp = C + (size_t)bh * NNX * NNX;
#pragma unroll
    for (int i = 0; i < 4; i++)
#pragma unroll
        for (int j = 0; j < 4; j++)
            Cp[(size_t)(m0 + tm * 4 + i) * NNX + n0 + tn * 4 + j] = acc[i][j];
}

// ======================= fused 18->6 channel mix + softmax =======================
__global__ __launch_bounds__(512)
void mix_softmax(const float* __restrict__ scale_p, const float* __restrict__ rs_p,
                 const float* __restrict__ gs_p, const float* __restrict__ conv_w,
                 const float* __restrict__ conv_b, float* __restrict__ attn_out)
{
    int bn = blockIdx.x;
    int b = bn >> 9, n = bn & 511;
    int t = threadIdx.x;               // m index
    __shared__ float cw[108], cb[6], sq4[6], sca[3];
    __shared__ float red2[16];
    if (t < 108) cw[t] = conv_w[t];
    if (t < 6) { cb[t] = conv_b[t]; sq4[t] = g_qn4[(b * 6 + t) * 512 + n]; }
    if (t == 120) sca[0] = scale_p[0];
    if (t == 121) sca[1] = rs_p[0];
    if (t == 122) sca[2] = gs_p[0];
    __syncthreads();

    float mix[6];
#pragma unroll
    for (int o = 0; o < 6; o++) mix[o] = cb[o];
#pragma unroll
    for (int h = 0; h < 6; h++) {
        size_t base = ((size_t)(b * 6 + h) * 512 + n) * 512 + t;
        float qk = g_qk[base];
        float dd = g_dd[base];
        float kn4 = g_kn4[(b * 6 + h) * 512 + t];
        float eu = qk * sca[0];
        float ri = sqrtf(fmaxf(sq4[h] + kn4 - 2.0f * qk * qk, 0.0f)) * sca[1];
        float gr = dd * dd * sca[2];
#pragma unroll
        for (int o = 0; o < 6; o++)
            mix[o] += cw[o * 18 + h] * eu + cw[o * 18 + 6 + h] * ri + cw[o * 18 + 12 + h] * gr;
    }

    int lane = t & 31, wid = t >> 5;
    for (int o = 0; o < 6; o++) {
        float v = mix[o];
#pragma unroll
        for (int of = 16; of; of >>= 1) v = fmaxf(v, __shfl_xor_sync(0xffffffffu, v, of));
        if (lane == 0) red2[wid] = v;
        __syncthreads();
        if (t < 32) {
            float x = (t < 16) ? red2[t] : -3.4e38f;
#pragma unroll
            for (int of = 8; of; of >>= 1) x = fmaxf(x, __shfl_xor_sync(0xffffffffu, x, of));
            if (t == 0) red2[0] = x;
        }
        __syncthreads();
        float mx = red2[0];
        __syncthreads();
        float e = expf(mix[o] - mx);
        float s = e;
#pragma unroll
        for (int of = 16; of; of >>= 1) s += __shfl_xor_sync(0xffffffffu, s, of);
        if (lane == 0) red2[wid] = s;
        __syncthreads();
        if (t < 32) {
            float x = (t < 16) ? red2[t] : 0.f;
#pragma unroll
            for (int of = 8; of; of >>= 1) x += __shfl_xor_sync(0xffffffffu, x, of);
            if (t == 0) red2[0] = x;
        }
        __syncthreads();
        float r = e / red2[0];
        attn_out[((size_t)(b * 6 + o) * 512 + n) * 512 + t] = r;
        __syncthreads();
    }
}

// ======================= batched attn @ V : C[bh][512,64], scattered to [B,N,C] =======================
__global__ __launch_bounds__(256)
void bgemm_av(const float* __restrict__ attn)
{
    __shared__ float As[32 * 68];
    __shared__ float Vs[32 * 68];
    int bh = blockIdx.y;
    int m0 = blockIdx.x * 64;
    int b = bh / 6, h = bh - b * 6;
    int t = threadIdx.x, tm = t >> 4, tn = t & 15;
    const float* Ap = attn + (size_t)bh * NNX * NNX;
    const float* Vp = g_v + (size_t)bh * NNX * HDX;
    float acc[4][4];
#pragma unroll
    for (int i = 0; i < 4; i++)
#pragma unroll
        for (int j = 0; j < 4; j++) acc[i][j] = 0.f;

    for (int kt = 0; kt < NNX; kt += 32) {
#pragma unroll
        for (int u = 0; u < 2; u++) {
            int p = t + u * 256;
            int r = p >> 3, cg = p & 7;
            float4 av = *(const float4*)(Ap + (size_t)(m0 + r) * NNX + kt + cg * 4);
            As[(cg * 4 + 0) * 68 + r] = av.x;
            As[(cg * 4 + 1) * 68 + r] = av.y;
            As[(cg * 4 + 2) * 68 + r] = av.z;
            As[(cg * 4 + 3) * 68 + r] = av.w;
            int r2 = p >> 4, cg2 = p & 15;
            float4 vv = *(const float4*)(Vp + (size_t)(kt + r2) * 64 + cg2 * 4);
            Vs[r2 * 68 + cg2 * 4 + 0] = vv.x;
            Vs[r2 * 68 + cg2 * 4 + 1] = vv.y;
            Vs[r2 * 68 + cg2 * 4 + 2] = vv.z;
            Vs[r2 * 68 + cg2 * 4 + 3] = vv.w;
        }
        __syncthreads();
#pragma unroll 8
        for (int k = 0; k < 32; k++) {
            float a[4], bv[4];
#pragma unroll
            for (int i = 0; i < 4; i++) a[i] = As[k * 68 + tm * 4 + i];
#pragma unroll
            for (int j = 0; j < 4; j++) bv[j] = Vs[k * 68 + tn * 4 + j];
#pragma unroll
            for (int i = 0; i < 4; i++)
#pragma unroll
                for (int j = 0; j < 4; j++) acc[i][j] += a[i] * bv[j];
        }
        __syncthreads();
    }
#pragma unroll
    for (int i = 0; i < 4; i++)
#pragma unroll
        for (int j = 0; j < 4; j++) {
            int m = m0 + tm * 4 + i;
            int nn = tn * 4 + j;
            g_attnv[(size_t)(b * 512 + m) * CCX + h * 64 + nn] = acc[i][j];
        }
}

// ======================= launch =======================
extern "C" void kernel_launch(void* const* d_in, const int* in_sizes, int n_in,
                              void* d_out, int out_size)
{
    const float* src    = (const float*)d_in[0];
    const float* pre_w  = (const float*)d_in[1];
    const float* pre_b  = (const float*)d_in[2];
    const float* qkv_w  = (const float*)d_in[3];
    const float* qkv_b  = (const float*)d_in[4];
    const float* scale  = (const float*)d_in[5];
    const float* riem   = (const float*)d_in[6];
    const float* grass  = (const float*)d_in[7];
    const float* conv_w = (const float*)d_in[8];
    const float* conv_b = (const float*)d_in[9];
    const float* proj_w = (const float*)d_in[10];
    const float* proj_b = (const float*)d_in[11];
    const float* n1_w   = (const float*)d_in[12];
    const float* n1_b   = (const float*)d_in[13];
    const float* l1_w   = (const float*)d_in[14];
    const float* l1_b   = (const float*)d_in[15];
    const float* l2_w   = (const float*)d_in[16];
    const float* l2_b   = (const float*)d_in[17];
    float* out = (float*)d_out;

    void *p_x, *p_q, *p_k, *p_qgr, *p_kgr, *p_qk, *p_dd, *p_attnv, *p_src1, *p_hff;
    cudaGetSymbolAddress(&p_x, g_x);
    cudaGetSymbolAddress(&p_q, g_q);
    cudaGetSymbolAddress(&p_k, g_k);
    cudaGetSymbolAddress(&p_qgr, g_qgr);
    cudaGetSymbolAddress(&p_kgr, g_kgr);
    cudaGetSymbolAddress(&p_qk, g_qk);
    cudaGetSymbolAddress(&p_dd, g_dd);
    cudaGetSymbolAddress(&p_attnv, g_attnv);
    cudaGetSymbolAddress(&p_src1, g_src1);
    cudaGetSymbolAddress(&p_hff, g_hff);

    // 1. pre-LN
    ln_kernel<<<MTOK, 128>>>(src, pre_w, pre_b, (float*)p_x);
    // 2. QKV projection, scattered into per-head q/k/v
    sgemm_abt<EPI_QKV><<<dim3(FFD / 64, MTOK / 128), 256>>>(
        (const float*)p_x, qkv_w, qkv_b, nullptr, nullptr, MTOK, FFD, CCX);
    // 3. row norms^4
    norms_kernel<<<(BHX * NNX + 255) / 256, 256>>>();
    // 4. register-resident Householder QR, q and k in one launch (192 blocks)
    qr_kernel2<<<2 * BHX, 512>>>((const float*)p_q, (float*)p_qgr,
                                 (const float*)p_k, (float*)p_kgr);
    // 5. score GEMMs
    bgemm_nt<<<dim3(8, 8, BHX), 256>>>((const float*)p_q, (const float*)p_k, (float*)p_qk);
    bgemm_nt<<<dim3(8, 8, BHX), 256>>>((const float*)p_qgr, (const float*)p_kgr, (float*)p_dd);
    // 6. fused channel-mix + softmax -> attn output region of d_out
    float* attn_out = out + OUT_ATTN_OFF;
    mix_softmax<<<MTOK, 512>>>(scale, riem, grass, conv_w, conv_b, attn_out);
    // 7. attn @ V -> [B,N,C] layout
    bgemm_av<<<dim3(8, BHX), 256>>>(attn_out);
    // 8. output projection + residual with original src
    sgemm_abt<EPI_RESID><<<dim3(CCX / 64, MTOK / 128), 256>>>(
        (const float*)p_attnv, proj_w, proj_b, src, (float*)p_src1, MTOK, CCX, CCX);
    // 9. norm1
    ln_kernel<<<MTOK, 128>>>((const float*)p_src1, n1_w, n1_b, (float*)p_x);
    // 10. FF lin1 + exact GELU
    sgemm_abt<EPI_GELU><<<dim3(FFD / 64, MTOK / 128), 256>>>(
        (const float*)p_x, l1_w, l1_b, nullptr, (float*)p_hff, MTOK, FFD, CCX);
    // 11. FF lin2 + residual (with the LN'd activations) -> src part of d_out
    sgemm_abt<EPI_RESID><<<dim3(CCX / 64, MTOK / 128), 256>>>(
        (const float*)p_hff, l2_w, l2_b, (const float*)p_x, out, MTOK, CCX, FFD);

    (void)in_sizes; (void)n_in; (void)out_size;
}

// round 7
// speedup vs baseline: 1.2784x; 1.2784x over previous
#include <cuda_runtime.h>
#include <math.h>
#include <stdint.h>

#define BB 16
#define NNX 512
#define CCX 384
#define HHX 6
#define HDX 64
#define FFD 1152
#define BHX (BB*HHX)        // 96
#define MTOK (BB*NNX)       // 8192
#define OUT_ATTN_OFF ((size_t)MTOK*CCX)   // 3145728

// ---------------- device scratch (no dynamic allocation allowed) ----------------
__device__ float g_x[MTOK*CCX];
__device__ float g_q[BHX*NNX*HDX];
__device__ float g_k[BHX*NNX*HDX];
__device__ float g_v[BHX*NNX*HDX];
__device__ float g_qgr[BHX*NNX*HDX];
__device__ float g_kgr[BHX*NNX*HDX];
__device__ float g_qn4[BHX*NNX];
__device__ float g_kn4[BHX*NNX];
__device__ float g_qk[BHX*NNX*NNX];
__device__ float g_dd[BHX*NNX*NNX];
__device__ float g_attnv[MTOK*CCX];
__device__ float g_src1[MTOK*CCX];
__device__ float g_hff[MTOK*FFD];

// ======================= LayerNorm (row of 384, 128 threads) =======================
__global__ void ln_kernel(const float* __restrict__ in, const float* __restrict__ w,
                          const float* __restrict__ b, float* __restrict__ out)
{
    int row = blockIdx.x;
    int t = threadIdx.x;
    const float* p = in + (size_t)row * CCX;
    float v0 = p[t], v1 = p[t + 128], v2 = p[t + 256];
    __shared__ float sh[4];
    float s = v0 + v1 + v2;
#pragma unroll
    for (int o = 16; o; o >>= 1) s += __shfl_xor_sync(0xffffffffu, s, o);
    if ((t & 31) == 0) sh[t >> 5] = s;
    __syncthreads();
    float mu = (sh[0] + sh[1] + sh[2] + sh[3]) * (1.0f / CCX);
    __syncthreads();
    float d0 = v0 - mu, d1 = v1 - mu, d2 = v2 - mu;
    float s2 = d0 * d0 + d1 * d1 + d2 * d2;
#pragma unroll
    for (int o = 16; o; o >>= 1) s2 += __shfl_xor_sync(0xffffffffu, s2, o);
    if ((t & 31) == 0) sh[t >> 5] = s2;
    __syncthreads();
    float var = (sh[0] + sh[1] + sh[2] + sh[3]) * (1.0f / CCX);
    float r = rsqrtf(var + 1e-5f);
    float* q = out + (size_t)row * CCX;
    q[t]       = d0 * r * w[t]       + b[t];
    q[t + 128] = d1 * r * w[t + 128] + b[t + 128];
    q[t + 256] = d2 * r * w[t + 256] + b[t + 256];
}

// ======================= generic SGEMM: C[M,L] = A[M,K] @ W[L,K]^T + bias =======================
#define EPI_NONE 0
#define EPI_QKV  1
#define EPI_GELU 2
#define EPI_RESID 3

template<int EPI>
__global__ __launch_bounds__(256)
void sgemm_abt(const float* __restrict__ A, const float* __restrict__ W,
               const float* __restrict__ bias, const float* __restrict__ resid,
               float* __restrict__ C, int M, int L, int K)
{
    __shared__ float As[16 * 132];
    __shared__ float Ws[16 * 68];
    int m0 = blockIdx.y * 128;
    int l0 = blockIdx.x * 64;
    int t = threadIdx.x;
    int tm = t >> 4, tn = t & 15;
    float acc[8][4];
#pragma unroll
    for (int i = 0; i < 8; i++)
#pragma unroll
        for (int j = 0; j < 4; j++) acc[i][j] = 0.f;

    for (int kt = 0; kt < K; kt += 16) {
#pragma unroll
        for (int u = 0; u < 2; u++) {
            int p = t + u * 256;
            int r = p >> 2, cg = p & 3;
            float4 av = *(const float4*)(A + (size_t)(m0 + r) * K + kt + cg * 4);
            As[(cg * 4 + 0) * 132 + r] = av.x;
            As[(cg * 4 + 1) * 132 + r] = av.y;
            As[(cg * 4 + 2) * 132 + r] = av.z;
            As[(cg * 4 + 3) * 132 + r] = av.w;
        }
        {
            int r = t >> 2, cg = t & 3;
            float4 wv = *(const float4*)(W + (size_t)(l0 + r) * K + kt + cg * 4);
            Ws[(cg * 4 + 0) * 68 + r] = wv.x;
            Ws[(cg * 4 + 1) * 68 + r] = wv.y;
            Ws[(cg * 4 + 2) * 68 + r] = wv.z;
            Ws[(cg * 4 + 3) * 68 + r] = wv.w;
        }
        __syncthreads();
#pragma unroll
        for (int k = 0; k < 16; k++) {
            float a[8], bv[4];
#pragma unroll
            for (int i = 0; i < 8; i++) a[i] = As[k * 132 + tm * 8 + i];
#pragma unroll
            for (int j = 0; j < 4; j++) bv[j] = Ws[k * 68 + tn * 4 + j];
#pragma unroll
            for (int i = 0; i < 8; i++)
#pragma unroll
                for (int j = 0; j < 4; j++) acc[i][j] += a[i] * bv[j];
        }
        __syncthreads();
    }

#pragma unroll
    for (int i = 0; i < 8; i++) {
#pragma unroll
        for (int j = 0; j < 4; j++) {
            int row = m0 + tm * 8 + i;
            int col = l0 + tn * 4 + j;
            float val = acc[i][j] + bias[col];
            if (EPI == EPI_NONE) {
                C[(size_t)row * L + col] = val;
            } else if (EPI == EPI_GELU) {
                C[(size_t)row * L + col] = 0.5f * val * (1.0f + erff(val * 0.70710678118654752f));
            } else if (EPI == EPI_RESID) {
                C[(size_t)row * L + col] = val + resid[(size_t)row * L + col];
            } else { // QKV scatter
                int three = col / 384;
                int rem = col - three * 384;
                int h = rem >> 6, d = rem & 63;
                int b = row >> 9, n = row & 511;
                float* dst = (three == 0) ? g_q : ((three == 1) ? g_k : g_v);
                dst[((size_t)(b * 6 + h) * 512 + n) * 64 + d] = val;
            }
        }
    }
}

// ======================= per-row squared-norms^2 =======================
__global__ void norms_kernel()
{
    int idx = blockIdx.x * 256 + threadIdx.x;
    if (idx >= BHX * NNX) return;
    const float* pq = g_q + (size_t)idx * 64;
    const float* pk = g_k + (size_t)idx * 64;
    float sq = 0.f, sk = 0.f;
#pragma unroll
    for (int d = 0; d < 64; d++) { sq += pq[d] * pq[d]; sk += pk[d] * pk[d]; }
    g_qn4[idx] = sq * sq;
    g_kn4[idx] = sk * sk;
}

// ======================= register-resident Householder QR (512x64, reduced Q) =======================
// One block per matrix, 512 threads. Warp w owns columns 4w..4w+3;
// lane l owns rows 16l..16l+15. Each thread keeps a 4x16 register tile.
// ALL register-array indices are compile-time (unrolled cc loop with cc==jc guard)
// so the tile stays in registers — no local-memory demotion.
// vsh is double-buffered so only ONE __syncthreads per Householder step is needed.
// LAPACK sgeqr2 + sorg2r conventions (beta = -copysign(|x|, alpha)).
__global__ __launch_bounds__(512, 1)
void qr_kernel2(const float* __restrict__ X0, float* __restrict__ Q0,
                const float* __restrict__ X1, float* __restrict__ Q1)
{
    int bh = blockIdx.x;
    const float* src = (bh < BHX) ? (X0 + (size_t)bh * 512 * 64)
                                  : (X1 + (size_t)(bh - BHX) * 512 * 64);
    float* dst = (bh < BHX) ? (Q0 + (size_t)bh * 512 * 64)
                            : (Q1 + (size_t)(bh - BHX) * 512 * 64);
    int t = threadIdx.x;
    int w = t >> 5, l = t & 31;
    __shared__ float vsh[2][512];
    __shared__ float tauv[64];

    float a[4][16];
#pragma unroll
    for (int r = 0; r < 16; r++) {
        float4 v4 = *(const float4*)(src + (size_t)(16 * l + r) * 64 + 4 * w);
        a[0][r] = v4.x; a[1][r] = v4.y; a[2][r] = v4.z; a[3][r] = v4.w;
    }

    // ---------------- geqrf ----------------
    for (int j = 0; j < 64; j++) {
        int jw = j >> 2, jc = j & 3;
        float* vb = vsh[j & 1];
        if (w == jw) {
#pragma unroll
            for (int cc = 0; cc < 4; cc++) if (cc == jc) {
                float n2 = 0.f, al = 0.f;
#pragma unroll
                for (int r = 0; r < 16; r++) {
                    int i = 16 * l + r;
                    float x = a[cc][r];
                    n2 += (i > j) ? x * x : 0.f;
                    al += (i == j) ? x : 0.f;
                }
#pragma unroll
                for (int o = 16; o; o >>= 1) {
                    n2 += __shfl_xor_sync(0xffffffffu, n2, o);
                    al += __shfl_xor_sync(0xffffffffu, al, o);
                }
                float tau, scal;
                if (n2 == 0.f) { tau = 0.f; scal = 0.f; }
                else {
                    float beta = -copysignf(sqrtf(al * al + n2), al);
                    tau  = (beta - al) / beta;
                    scal = 1.0f / (al - beta);
                }
#pragma unroll
                for (int r = 0; r < 16; r++) {
                    int i = 16 * l + r;
                    float vv;
                    if (i < j) vv = 0.f;
                    else if (i == j) vv = 1.f;
                    else { vv = a[cc][r] * scal; a[cc][r] = vv; }
                    vb[i] = vv;
                }
                if (l == 0) tauv[j] = tau;
            }
        }
        __syncthreads();
        float tau = tauv[j];
        if (tau != 0.f && (4 * w + 3) > j) {
            float vr[16];
#pragma unroll
            for (int r = 0; r < 16; r++) vr[r] = vb[16 * l + r];
#pragma unroll
            for (int c = 0; c < 4; c++) {
                int C = 4 * w + c;
                if (C > j) {
                    float s = 0.f;
#pragma unroll
                    for (int r = 0; r < 16; r++) s += vr[r] * a[c][r];
#pragma unroll
                    for (int o = 16; o; o >>= 1) s += __shfl_xor_sync(0xffffffffu, s, o);
                    float wc = tau * s;
#pragma unroll
                    for (int r = 0; r < 16; r++) a[c][r] -= vr[r] * wc;
                }
            }
        }
        // no trailing barrier: vsh is double-buffered; the next write to this
        // buffer happens after the NEXT step's barrier, which every warp only
        // passes after finishing this step's reads.
    }
    __syncthreads();

    // ---------------- org2r (backward, in place) ----------------
    for (int j = 63; j >= 0; j--) {
        int jw = j >> 2, jc = j & 3;
        float tau = tauv[j];
        float* vb = vsh[j & 1];
        if (w == jw) {
#pragma unroll
            for (int cc = 0; cc < 4; cc++) if (cc == jc) {
#pragma unroll
                for (int r = 0; r < 16; r++) {
                    int i = 16 * l + r;
                    float vv;
                    if (i < j) vv = 0.f;
                    else if (i == j) vv = 1.f;
                    else vv = a[cc][r];
                    vb[i] = vv;
                }
            }
        }
        __syncthreads();
        if (tau != 0.f && (4 * w + 3) > j) {
            float vr[16];
#pragma unroll
            for (int r = 0; r < 16; r++) vr[r] = vb[16 * l + r];
#pragma unroll
            for (int c = 0; c < 4; c++) {
                int C = 4 * w + c;
                if (C > j) {
                    float s = 0.f;
#pragma unroll
                    for (int r = 0; r < 16; r++) s += vr[r] * a[c][r];
#pragma unroll
                    for (int o = 16; o; o >>= 1) s += __shfl_xor_sync(0xffffffffu, s, o);
                    float wc = tau * s;
#pragma unroll
                    for (int r = 0; r < 16; r++) a[c][r] -= vr[r] * wc;
                }
            }
        }
        // owner converts column j into a Q column (register-local, no sync needed)
        if (w == jw) {
#pragma unroll
            for (int cc = 0; cc < 4; cc++) if (cc == jc) {
#pragma unroll
                for (int r = 0; r < 16; r++) {
                    int i = 16 * l + r;
                    float val;
                    if (i < j) val = 0.f;
                    else if (i == j) val = 1.f - tau;
                    else val = -tau * a[cc][r];
                    a[cc][r] = val;
                }
            }
        }
    }
    __syncthreads();

#pragma unroll
    for (int r = 0; r < 16; r++) {
        float4 v4 = make_float4(a[0][r], a[1][r], a[2][r], a[3][r]);
        *(float4*)(dst + (size_t)(16 * l + r) * 64 + 4 * w) = v4;
    }
}

// ======================= batched NT GEMM: C[bh][512,512] = X[bh][512,64] @ Y[bh][512,64]^T =======================
__global__ __launch_bounds__(256)
void bgemm_nt(const float* __restrict__ X, const float* __restrict__ Y, float* __restrict__ C)
{
    __shared__ float Xs[64 * 68];
    __shared__ float Ys[64 * 68];
    int bh = blockIdx.z;
    int m0 = blockIdx.y * 64, n0 = blockIdx.x * 64;
    int t = threadIdx.x, tm = t >> 4, tn = t & 15;
    const float* Xp = X + (size_t)bh * NNX * HDX;
    const float* Yp = Y + (size_t)bh * NNX * HDX;
#pragma unroll
    for (int u = 0; u < 4; u++) {
        int p = t + u * 256;
        int r = p >> 4, cg = p & 15;
        float4 xv = *(const float4*)(Xp + (size_t)(m0 + r) * 64 + cg * 4);
        Xs[(cg * 4 + 0) * 68 + r] = xv.x;
        Xs[(cg * 4 + 1) * 68 + r] = xv.y;
        Xs[(cg * 4 + 2) * 68 + r] = xv.z;
        Xs[(cg * 4 + 3) * 68 + r] = xv.w;
        float4 yv = *(const float4*)(Yp + (size_t)(n0 + r) * 64 + cg * 4);
        Ys[(cg * 4 + 0) * 68 + r] = yv.x;
        Ys[(cg * 4 + 1) * 68 + r] = yv.y;
        Ys[(cg * 4 + 2) * 68 + r] = yv.z;
        Ys[(cg * 4 + 3) * 68 + r] = yv.w;
    }
    __syncthreads();
    float acc[4][4];
#pragma unroll
    for (int i = 0; i < 4; i++)
#pragma unroll
        for (int j = 0; j < 4; j++) acc[i][j] = 0.f;
#pragma unroll 16
    for (int k = 0; k < 64; k++) {
        float a[4], b[4];
#pragma unroll
        for (int i = 0; i < 4; i++) a[i] = Xs[k * 68 + tm * 4 + i];
#pragma unroll
        for (int j = 0; j < 4; j++) b[j] = Ys[k * 68 + tn * 4 + j];
#pragma unroll
        for (int i = 0; i < 4; i++)
#pragma unroll
            for (int j = 0; j < 4; j++) acc[i][j] += a[i] * b[j];
    }
    float* Cp = C + (size_t)bh * NNX * NNX;
#pragma unroll
    for (int i = 0; i < 4; i++)
#pragma unroll
        for (int j = 0; j < 4; j++)
            Cp[(size_t)(m0 + tm * 4 + i) * NNX + n0 + tn * 4 + j] = acc[i][j];
}

// ======================= fused 18->6 channel mix + softmax =======================
__global__ __launch_bounds__(512)
void mix_softmax(const float* __restrict__ scale_p, const float* __restrict__ rs_p,
                 const float* __restrict__ gs_p, const float* __restrict__ conv_w,
                 const float* __restrict__ conv_b, float* __restrict__ attn_out)
{
    int bn = blockIdx.x;
    int b = bn >> 9, n = bn & 511;
    int t = threadIdx.x;               // m index
    __shared__ float cw[108], cb[6], sq4[6], sca[3];
    __shared__ float red2[16];
    if (t < 108) cw[t] = conv_w[t];
    if (t < 6) { cb[t] = conv_b[t]; sq4[t] = g_qn4[(b * 6 + t) * 512 + n]; }
    if (t == 120) sca[0] = scale_p[0];
    if (t == 121) sca[1] = rs_p[0];
    if (t == 122) sca[2] = gs_p[0];
    __syncthreads();

    float mix[6];
#pragma unroll
    for (int o = 0; o < 6; o++) mix[o] = cb[o];
#pragma unroll
    for (int h = 0; h < 6; h++) {
        size_t base = ((size_t)(b * 6 + h) * 512 + n) * 512 + t;
        float qk = g_qk[base];
        float dd = g_dd[base];
        float kn4 = g_kn4[(b * 6 + h) * 512 + t];
        float eu = qk * sca[0];
        float ri = sqrtf(fmaxf(sq4[h] + kn4 - 2.0f * qk * qk, 0.0f)) * sca[1];
        float gr = dd * dd * sca[2];
#pragma unroll
        for (int o = 0; o < 6; o++)
            mix[o] += cw[o * 18 + h] * eu + cw[o * 18 + 6 + h] * ri + cw[o * 18 + 12 + h] * gr;
    }

    int lane = t & 31, wid = t >> 5;
    for (int o = 0; o < 6; o++) {
        float v = mix[o];
#pragma unroll
        for (int of = 16; of; of >>= 1) v = fmaxf(v, __shfl_xor_sync(0xffffffffu, v, of));
        if (lane == 0) red2[wid] = v;
        __syncthreads();
        if (t < 32) {
            float x = (t < 16) ? red2[t] : -3.4e38f;
#pragma unroll
            for (int of = 8; of; of >>= 1) x = fmaxf(x, __shfl_xor_sync(0xffffffffu, x, of));
            if (t == 0) red2[0] = x;
        }
        __syncthreads();
        float mx = red2[0];
        __syncthreads();
        float e = expf(mix[o] - mx);
        float s = e;
#pragma unroll
        for (int of = 16; of; of >>= 1) s += __shfl_xor_sync(0xffffffffu, s, of);
        if (lane == 0) red2[wid] = s;
        __syncthreads();
        if (t < 32) {
            float x = (t < 16) ? red2[t] : 0.f;
#pragma unroll
            for (int of = 8; of; of >>= 1) x += __shfl_xor_sync(0xffffffffu, x, of);
            if (t == 0) red2[0] = x;
        }
        __syncthreads();
        float r = e / red2[0];
        attn_out[((size_t)(b * 6 + o) * 512 + n) * 512 + t] = r;
        __syncthreads();
    }
}

// ======================= batched attn @ V : C[bh][512,64], scattered to [B,N,C] =======================
__global__ __launch_bounds__(256)
void bgemm_av(const float* __restrict__ attn)
{
    __shared__ float As[32 * 68];
    __shared__ float Vs[32 * 68];
    int bh = blockIdx.y;
    int m0 = blockIdx.x * 64;
    int b = bh / 6, h = bh - b * 6;
    int t = threadIdx.x, tm = t >> 4, tn = t & 15;
    const float* Ap = attn + (size_t)bh * NNX * NNX;
    const float* Vp = g_v + (size_t)bh * NNX * HDX;
    float acc[4][4];
#pragma unroll
    for (int i = 0; i < 4; i++)
#pragma unroll
        for (int j = 0; j < 4; j++) acc[i][j] = 0.f;

    for (int kt = 0; kt < NNX; kt += 32) {
#pragma unroll
        for (int u = 0; u < 2; u++) {
            int p = t + u * 256;
            int r = p >> 3, cg = p & 7;
            float4 av = *(const float4*)(Ap + (size_t)(m0 + r) * NNX + kt + cg * 4);
            As[(cg * 4 + 0) * 68 + r] = av.x;
            As[(cg * 4 + 1) * 68 + r] = av.y;
            As[(cg * 4 + 2) * 68 + r] = av.z;
            As[(cg * 4 + 3) * 68 + r] = av.w;
            int r2 = p >> 4, cg2 = p & 15;
            float4 vv = *(const float4*)(Vp + (size_t)(kt + r2) * 64 + cg2 * 4);
            Vs[r2 * 68 + cg2 * 4 + 0] = vv.x;
            Vs[r2 * 68 + cg2 * 4 + 1] = vv.y;
            Vs[r2 * 68 + cg2 * 4 + 2] = vv.z;
            Vs[r2 * 68 + cg2 * 4 + 3] = vv.w;
        }
        __syncthreads();
#pragma unroll 8
        for (int k = 0; k < 32; k++) {
            float a[4], bv[4];
#pragma unroll
            for (int i = 0; i < 4; i++) a[i] = As[k * 68 + tm * 4 + i];
#pragma unroll
            for (int j = 0; j < 4; j++) bv[j] = Vs[k * 68 + tn * 4 + j];
#pragma unroll
            for (int i = 0; i < 4; i++)
#pragma unroll
                for (int j = 0; j < 4; j++) acc[i][j] += a[i] * bv[j];
        }
        __syncthreads();
    }
#pragma unroll
    for (int i = 0; i < 4; i++)
#pragma unroll
        for (int j = 0; j < 4; j++) {
            int m = m0 + tm * 4 + i;
            int nn = tn * 4 + j;
            g_attnv[(size_t)(b * 512 + m) * CCX + h * 64 + nn] = acc[i][j];
        }
}

// ======================= launch =======================
extern "C" void kernel_launch(void* const* d_in, const int* in_sizes, int n_in,
                              void* d_out, int out_size)
{
    const float* src    = (const float*)d_in[0];
    const float* pre_w  = (const float*)d_in[1];
    const float* pre_b  = (const float*)d_in[2];
    const float* qkv_w  = (const float*)d_in[3];
    const float* qkv_b  = (const float*)d_in[4];
    const float* scale  = (const float*)d_in[5];
    const float* riem   = (const float*)d_in[6];
    const float* grass  = (const float*)d_in[7];
    const float* conv_w = (const float*)d_in[8];
    const float* conv_b = (const float*)d_in[9];
    const float* proj_w = (const float*)d_in[10];
    const float* proj_b = (const float*)d_in[11];
    const float* n1_w   = (const float*)d_in[12];
    const float* n1_b   = (const float*)d_in[13];
    const float* l1_w   = (const float*)d_in[14];
    const float* l1_b   = (const float*)d_in[15];
    const float* l2_w   = (const float*)d_in[16];
    const float* l2_b   = (const float*)d_in[17];
    float* out = (float*)d_out;

    void *p_x, *p_q, *p_k, *p_qgr, *p_kgr, *p_qk, *p_dd, *p_attnv, *p_src1, *p_hff;
    cudaGetSymbolAddress(&p_x, g_x);
    cudaGetSymbolAddress(&p_q, g_q);
    cudaGetSymbolAddress(&p_k, g_k);
    cudaGetSymbolAddress(&p_qgr, g_qgr);
    cudaGetSymbolAddress(&p_kgr, g_kgr);
    cudaGetSymbolAddress(&p_qk, g_qk);
    cudaGetSymbolAddress(&p_dd, g_dd);
    cudaGetSymbolAddress(&p_attnv, g_attnv);
    cudaGetSymbolAddress(&p_src1, g_src1);
    cudaGetSymbolAddress(&p_hff, g_hff);

    // 1. pre-LN
    ln_kernel<<<MTOK, 128>>>(src, pre_w, pre_b, (float*)p_x);
    // 2. QKV projection, scattered into per-head q/k/v
    sgemm_abt<EPI_QKV><<<dim3(FFD / 64, MTOK / 128), 256>>>(
        (const float*)p_x, qkv_w, qkv_b, nullptr, nullptr, MTOK, FFD, CCX);
    // 3. row norms^4
    norms_kernel<<<(BHX * NNX + 255) / 256, 256>>>();
    // 4. register-resident Householder QR, q and k in one launch (192 blocks)
    qr_kernel2<<<2 * BHX, 512>>>((const float*)p_q, (float*)p_qgr,
                                 (const float*)p_k, (float*)p_kgr);
    // 5. score GEMMs
    bgemm_nt<<<dim3(8, 8, BHX), 256>>>((const float*)p_q, (const float*)p_k, (float*)p_qk);
    bgemm_nt<<<dim3(8, 8, BHX), 256>>>((const float*)p_qgr, (const float*)p_kgr, (float*)p_dd);
    // 6. fused channel-mix + softmax -> attn output region of d_out
    float* attn_out = out + OUT_ATTN_OFF;
    mix_softmax<<<MTOK, 512>>>(scale, riem, grass, conv_w, conv_b, attn_out);
    // 7. attn @ V -> [B,N,C] layout
    bgemm_av<<<dim3(8, BHX), 256>>>(attn_out);
    // 8. output projection + residual with original src
    sgemm_abt<EPI_RESID><<<dim3(CCX / 64, MTOK / 128), 256>>>(
        (const float*)p_attnv, proj_w, proj_b, src, (float*)p_src1, MTOK, CCX, CCX);
    // 9. norm1
    ln_kernel<<<MTOK, 128>>>((const float*)p_src1, n1_w, n1_b, (float*)p_x);
    // 10. FF lin1 + exact GELU
    sgemm_abt<EPI_GELU><<<dim3(FFD / 64, MTOK / 128), 256>>>(
        (const float*)p_x, l1_w, l1_b, nullptr, (float*)p_hff, MTOK, FFD, CCX);
    // 11. FF lin2 + residual (with the LN'd activations) -> src part of d_out
    sgemm_abt<EPI_RESID><<<dim3(CCX / 64, MTOK / 128), 256>>>(
        (const float*)p_hff, l2_w, l2_b, (const float*)p_x, out, MTOK, CCX, FFD);

    (void)in_sizes; (void)n_in; (void)out_size;
}

// round 8
// speedup vs baseline: 1.6697x; 1.3061x over previous
#include <cuda_runtime.h>
#include <math.h>
#include <stdint.h>

#define BB 16
#define NNX 512
#define CCX 384
#define HHX 6
#define HDX 64
#define FFD 1152
#define BHX (BB*HHX)        // 96
#define MTOK (BB*NNX)       // 8192
#define OUT_ATTN_OFF ((size_t)MTOK*CCX)   // 3145728

// ---------------- device scratch (no dynamic allocation allowed) ----------------
__device__ float g_x[MTOK*CCX];
__device__ float g_q[BHX*NNX*HDX];
__device__ float g_k[BHX*NNX*HDX];
__device__ float g_v[BHX*NNX*HDX];
__device__ float g_qgr[BHX*NNX*HDX];
__device__ float g_kgr[BHX*NNX*HDX];
__device__ float g_qn4[BHX*NNX];
__device__ float g_kn4[BHX*NNX];
__device__ float g_qk[BHX*NNX*NNX];
__device__ float g_dd[BHX*NNX*NNX];
__device__ float g_attnv[MTOK*CCX];
__device__ float g_src1[MTOK*CCX];
__device__ float g_hff[MTOK*FFD];

// ======================= LayerNorm (row of 384, 128 threads) =======================
__global__ void ln_kernel(const float* __restrict__ in, const float* __restrict__ w,
                          const float* __restrict__ b, float* __restrict__ out)
{
    int row = blockIdx.x;
    int t = threadIdx.x;
    const float* p = in + (size_t)row * CCX;
    float v0 = p[t], v1 = p[t + 128], v2 = p[t + 256];
    __shared__ float sh[4];
    float s = v0 + v1 + v2;
#pragma unroll
    for (int o = 16; o; o >>= 1) s += __shfl_xor_sync(0xffffffffu, s, o);
    if ((t & 31) == 0) sh[t >> 5] = s;
    __syncthreads();
    float mu = (sh[0] + sh[1] + sh[2] + sh[3]) * (1.0f / CCX);
    __syncthreads();
    float d0 = v0 - mu, d1 = v1 - mu, d2 = v2 - mu;
    float s2 = d0 * d0 + d1 * d1 + d2 * d2;
#pragma unroll
    for (int o = 16; o; o >>= 1) s2 += __shfl_xor_sync(0xffffffffu, s2, o);
    if ((t & 31) == 0) sh[t >> 5] = s2;
    __syncthreads();
    float var = (sh[0] + sh[1] + sh[2] + sh[3]) * (1.0f / CCX);
    float r = rsqrtf(var + 1e-5f);
    float* q = out + (size_t)row * CCX;
    q[t]       = d0 * r * w[t]       + b[t];
    q[t + 128] = d1 * r * w[t + 128] + b[t + 128];
    q[t + 256] = d2 * r * w[t + 256] + b[t + 256];
}

// ======================= tf32 helpers =======================
__device__ __forceinline__ uint32_t f2tf32(float x) {
    uint32_t r;
    asm("cvt.rna.tf32.f32 %0, %1;" : "=r"(r) : "f"(x));
    return r;
}

__device__ __forceinline__ void mma_tf32(float& d0, float& d1, float& d2, float& d3,
                                         uint32_t a0, uint32_t a1, uint32_t a2, uint32_t a3,
                                         uint32_t b0, uint32_t b1) {
    asm volatile(
        "mma.sync.aligned.m16n8k8.row.col.f32.tf32.tf32.f32 "
        "{%0,%1,%2,%3}, {%4,%5,%6,%7}, {%8,%9}, {%0,%1,%2,%3};\n"
        : "+f"(d0), "+f"(d1), "+f"(d2), "+f"(d3)
        : "r"(a0), "r"(a1), "r"(a2), "r"(a3), "r"(b0), "r"(b1));
}

// ======================= tf32 mma GEMM: C[M,L] = A[M,K] @ W[L,K]^T + bias =======================
// CTA tile 128x128, 8 warps (2 m x 4 n), warp tile 64x32, k-tile 16.
// Smem stride 20 floats -> fragment LDS is bank-conflict-free.
#define EPI_NONE 0
#define EPI_QKV  1
#define EPI_GELU 2
#define EPI_RESID 3

template<int EPI>
__global__ __launch_bounds__(256)
void mmgemm_abt(const float* __restrict__ A, const float* __restrict__ W,
                const float* __restrict__ bias, const float* __restrict__ resid,
                float* __restrict__ C, int M, int L, int K)
{
    __shared__ uint32_t As[128 * 20];
    __shared__ uint32_t Ws[128 * 20];
    int m0 = blockIdx.y * 128;
    int l0 = blockIdx.x * 128;
    int t = threadIdx.x;
    int warp = t >> 5, lane = t & 31;
    int g = lane >> 2, tig = lane & 3;
    int wm = warp >> 2, wn = warp & 3;        // warp grid 2 x 4
    int mB = wm * 64, nB = wn * 32;

    float acc[4][4][4];
#pragma unroll
    for (int i = 0; i < 4; i++)
#pragma unroll
        for (int j = 0; j < 4; j++)
#pragma unroll
            for (int v = 0; v < 4; v++) acc[i][j][v] = 0.f;

    // per-thread global load coords (16 floats per array per k-tile)
    int lr = t >> 2;             // 0..63
    int lc = (t & 3) * 4;        // 0,4,8,12
    const float* Ap0 = A + (size_t)(m0 + lr) * K + lc;
    const float* Ap1 = A + (size_t)(m0 + 64 + lr) * K + lc;
    const float* Wp0 = W + (size_t)(l0 + lr) * K + lc;
    const float* Wp1 = W + (size_t)(l0 + 64 + lr) * K + lc;

    float4 rA0 = *(const float4*)(Ap0);
    float4 rA1 = *(const float4*)(Ap1);
    float4 rW0 = *(const float4*)(Wp0);
    float4 rW1 = *(const float4*)(Wp1);

    for (int kt = 0; kt < K; kt += 16) {
        // store staged tile (cvt to tf32)
        {
            uint32_t* as0 = As + lr * 20 + lc;
            uint32_t* as1 = As + (64 + lr) * 20 + lc;
            uint32_t* ws0 = Ws + lr * 20 + lc;
            uint32_t* ws1 = Ws + (64 + lr) * 20 + lc;
            as0[0] = f2tf32(rA0.x); as0[1] = f2tf32(rA0.y); as0[2] = f2tf32(rA0.z); as0[3] = f2tf32(rA0.w);
            as1[0] = f2tf32(rA1.x); as1[1] = f2tf32(rA1.y); as1[2] = f2tf32(rA1.z); as1[3] = f2tf32(rA1.w);
            ws0[0] = f2tf32(rW0.x); ws0[1] = f2tf32(rW0.y); ws0[2] = f2tf32(rW0.z); ws0[3] = f2tf32(rW0.w);
            ws1[0] = f2tf32(rW1.x); ws1[1] = f2tf32(rW1.y); ws1[2] = f2tf32(rW1.z); ws1[3] = f2tf32(rW1.w);
        }
        __syncthreads();
        // prefetch next tile
        if (kt + 16 < K) {
            rA0 = *(const float4*)(Ap0 + kt + 16);
            rA1 = *(const float4*)(Ap1 + kt + 16);
            rW0 = *(const float4*)(Wp0 + kt + 16);
            rW1 = *(const float4*)(Wp1 + kt + 16);
        }
        // compute 2 k8 steps
#pragma unroll
        for (int ks = 0; ks < 16; ks += 8) {
            uint32_t af[4][4], bf[4][2];
#pragma unroll
            for (int i = 0; i < 4; i++) {
                int base = (mB + i * 16 + g) * 20 + ks + tig;
                af[i][0] = As[base];
                af[i][1] = As[base + 8 * 20];
                af[i][2] = As[base + 4];
                af[i][3] = As[base + 8 * 20 + 4];
            }
#pragma unroll
            for (int j = 0; j < 4; j++) {
                int base = (nB + j * 8 + g) * 20 + ks + tig;
                bf[j][0] = Ws[base];
                bf[j][1] = Ws[base + 4];
            }
#pragma unroll
            for (int i = 0; i < 4; i++)
#pragma unroll
                for (int j = 0; j < 4; j++)
                    mma_tf32(acc[i][j][0], acc[i][j][1], acc[i][j][2], acc[i][j][3],
                             af[i][0], af[i][1], af[i][2], af[i][3],
                             bf[j][0], bf[j][1]);
        }
        __syncthreads();
    }

    // epilogue
#pragma unroll
    for (int i = 0; i < 4; i++) {
#pragma unroll
        for (int j = 0; j < 4; j++) {
            int r0 = m0 + mB + i * 16 + g;
            int c0 = l0 + nB + j * 8 + 2 * tig;
            float b0v = bias[c0], b1v = bias[c0 + 1];
#pragma unroll
            for (int half = 0; half < 2; half++) {
                int row = r0 + half * 8;
                float v0 = acc[i][j][half * 2 + 0] + b0v;
                float v1 = acc[i][j][half * 2 + 1] + b1v;
                if (EPI == EPI_NONE) {
                    *(float2*)&C[(size_t)row * L + c0] = make_float2(v0, v1);
                } else if (EPI == EPI_GELU) {
                    v0 = 0.5f * v0 * (1.0f + erff(v0 * 0.70710678118654752f));
                    v1 = 0.5f * v1 * (1.0f + erff(v1 * 0.70710678118654752f));
                    *(float2*)&C[(size_t)row * L + c0] = make_float2(v0, v1);
                } else if (EPI == EPI_RESID) {
                    const float2 rv = *(const float2*)&resid[(size_t)row * L + c0];
                    *(float2*)&C[(size_t)row * L + c0] = make_float2(v0 + rv.x, v1 + rv.y);
                } else { // QKV scatter
#pragma unroll
                    for (int e = 0; e < 2; e++) {
                        int col = c0 + e;
                        float val = (e == 0) ? v0 : v1;
                        int three = col / 384;
                        int rem = col - three * 384;
                        int h = rem >> 6, d = rem & 63;
                        int bb = row >> 9, n = row & 511;
                        float* dst = (three == 0) ? g_q : ((three == 1) ? g_k : g_v);
                        dst[((size_t)(bb * 6 + h) * 512 + n) * 64 + d] = val;
                    }
                }
            }
        }
    }
}

// ======================= per-row squared-norms^2 =======================
__global__ void norms_kernel()
{
    int idx = blockIdx.x * 256 + threadIdx.x;
    if (idx >= BHX * NNX) return;
    const float* pq = g_q + (size_t)idx * 64;
    const float* pk = g_k + (size_t)idx * 64;
    float sq = 0.f, sk = 0.f;
#pragma unroll
    for (int d = 0; d < 64; d++) { sq += pq[d] * pq[d]; sk += pk[d] * pk[d]; }
    g_qn4[idx] = sq * sq;
    g_kn4[idx] = sk * sk;
}

// ======================= register-resident Householder QR (512x64, reduced Q) =======================
__global__ __launch_bounds__(512, 1)
void qr_kernel2(const float* __restrict__ X0, float* __restrict__ Q0,
                const float* __restrict__ X1, float* __restrict__ Q1)
{
    int bh = blockIdx.x;
    const float* src = (bh < BHX) ? (X0 + (size_t)bh * 512 * 64)
                                  : (X1 + (size_t)(bh - BHX) * 512 * 64);
    float* dst = (bh < BHX) ? (Q0 + (size_t)bh * 512 * 64)
                            : (Q1 + (size_t)(bh - BHX) * 512 * 64);
    int t = threadIdx.x;
    int w = t >> 5, l = t & 31;
    __shared__ float vsh[2][512];
    __shared__ float tauv[64];

    float a[4][16];
#pragma unroll
    for (int r = 0; r < 16; r++) {
        float4 v4 = *(const float4*)(src + (size_t)(16 * l + r) * 64 + 4 * w);
        a[0][r] = v4.x; a[1][r] = v4.y; a[2][r] = v4.z; a[3][r] = v4.w;
    }

    // ---------------- geqrf ----------------
    for (int j = 0; j < 64; j++) {
        int jw = j >> 2, jc = j & 3;
        float* vb = vsh[j & 1];
        if (w == jw) {
#pragma unroll
            for (int cc = 0; cc < 4; cc++) if (cc == jc) {
                float n2 = 0.f, al = 0.f;
#pragma unroll
                for (int r = 0; r < 16; r++) {
                    int i = 16 * l + r;
                    float x = a[cc][r];
                    n2 += (i > j) ? x * x : 0.f;
                    al += (i == j) ? x : 0.f;
                }
#pragma unroll
                for (int o = 16; o; o >>= 1) {
                    n2 += __shfl_xor_sync(0xffffffffu, n2, o);
                    al += __shfl_xor_sync(0xffffffffu, al, o);
                }
                float tau, scal;
                if (n2 == 0.f) { tau = 0.f; scal = 0.f; }
                else {
                    float beta = -copysignf(sqrtf(al * al + n2), al);
                    tau  = (beta - al) / beta;
                    scal = 1.0f / (al - beta);
                }
#pragma unroll
                for (int r = 0; r < 16; r++) {
                    int i = 16 * l + r;
                    float vv;
                    if (i < j) vv = 0.f;
                    else if (i == j) vv = 1.f;
                    else { vv = a[cc][r] * scal; a[cc][r] = vv; }
                    vb[i] = vv;
                }
                if (l == 0) tauv[j] = tau;
            }
        }
        __syncthreads();
        float tau = tauv[j];
        if (tau != 0.f && (4 * w + 3) > j) {
            float vr[16];
#pragma unroll
            for (int r = 0; r < 16; r++) vr[r] = vb[16 * l + r];
#pragma unroll
            for (int c = 0; c < 4; c++) {
                int C = 4 * w + c;
                if (C > j) {
                    float s = 0.f;
#pragma unroll
                    for (int r = 0; r < 16; r++) s += vr[r] * a[c][r];
#pragma unroll
                    for (int o = 16; o; o >>= 1) s += __shfl_xor_sync(0xffffffffu, s, o);
                    float wc = tau * s;
#pragma unroll
                    for (int r = 0; r < 16; r++) a[c][r] -= vr[r] * wc;
                }
            }
        }
    }
    __syncthreads();

    // ---------------- org2r (backward, in place) ----------------
    for (int j = 63; j >= 0; j--) {
        int jw = j >> 2, jc = j & 3;
        float tau = tauv[j];
        float* vb = vsh[j & 1];
        if (w == jw) {
#pragma unroll
            for (int cc = 0; cc < 4; cc++) if (cc == jc) {
#pragma unroll
                for (int r = 0; r < 16; r++) {
                    int i = 16 * l + r;
                    float vv;
                    if (i < j) vv = 0.f;
                    else if (i == j) vv = 1.f;
                    else vv = a[cc][r];
                    vb[i] = vv;
                }
            }
        }
        __syncthreads();
        if (tau != 0.f && (4 * w + 3) > j) {
            float vr[16];
#pragma unroll
            for (int r = 0; r < 16; r++) vr[r] = vb[16 * l + r];
#pragma unroll
            for (int c = 0; c < 4; c++) {
                int C = 4 * w + c;
                if (C > j) {
                    float s = 0.f;
#pragma unroll
                    for (int r = 0; r < 16; r++) s += vr[r] * a[c][r];
#pragma unroll
                    for (int o = 16; o; o >>= 1) s += __shfl_xor_sync(0xffffffffu, s, o);
                    float wc = tau * s;
#pragma unroll
                    for (int r = 0; r < 16; r++) a[c][r] -= vr[r] * wc;
                }
            }
        }
        if (w == jw) {
#pragma unroll
            for (int cc = 0; cc < 4; cc++) if (cc == jc) {
#pragma unroll
                for (int r = 0; r < 16; r++) {
                    int i = 16 * l + r;
                    float val;
                    if (i < j) val = 0.f;
                    else if (i == j) val = 1.f - tau;
                    else val = -tau * a[cc][r];
                    a[cc][r] = val;
                }
            }
        }
    }
    __syncthreads();

#pragma unroll
    for (int r = 0; r < 16; r++) {
        float4 v4 = make_float4(a[0][r], a[1][r], a[2][r], a[3][r]);
        *(float4*)(dst + (size_t)(16 * l + r) * 64 + 4 * w) = v4;
    }
}

// ======================= batched NT GEMM: C[bh][512,512] = X[bh][512,64] @ Y[bh][512,64]^T =======================
__global__ __launch_bounds__(256)
void bgemm_nt(const float* __restrict__ X, const float* __restrict__ Y, float* __restrict__ C)
{
    __shared__ float Xs[64 * 68];
    __shared__ float Ys[64 * 68];
    int bh = blockIdx.z;
    int m0 = blockIdx.y * 64, n0 = blockIdx.x * 64;
    int t = threadIdx.x, tm = t >> 4, tn = t & 15;
    const float* Xp = X + (size_t)bh * NNX * HDX;
    const float* Yp = Y + (size_t)bh * NNX * HDX;
#pragma unroll
    for (int u = 0; u < 4; u++) {
        int p = t + u * 256;
        int r = p >> 4, cg = p & 15;
        float4 xv = *(const float4*)(Xp + (size_t)(m0 + r) * 64 + cg * 4);
        Xs[(cg * 4 + 0) * 68 + r] = xv.x;
        Xs[(cg * 4 + 1) * 68 + r] = xv.y;
        Xs[(cg * 4 + 2) * 68 + r] = xv.z;
        Xs[(cg * 4 + 3) * 68 + r] = xv.w;
        float4 yv = *(const float4*)(Yp + (size_t)(n0 + r) * 64 + cg * 4);
        Ys[(cg * 4 + 0) * 68 + r] = yv.x;
        Ys[(cg * 4 + 1) * 68 + r] = yv.y;
        Ys[(cg * 4 + 2) * 68 + r] = yv.z;
        Ys[(cg * 4 + 3) * 68 + r] = yv.w;
    }
    __syncthreads();
    float acc[4][4];
#pragma unroll
    for (int i = 0; i < 4; i++)
#pragma unroll
        for (int j = 0; j < 4; j++) acc[i][j] = 0.f;
#pragma unroll 16
    for (int k = 0; k < 64; k++) {
        float a[4], b[4];
#pragma unroll
        for (int i = 0; i < 4; i++) a[i] = Xs[k * 68 + tm * 4 + i];
#pragma unroll
        for (int j = 0; j < 4; j++) b[j] = Ys[k * 68 + tn * 4 + j];
#pragma unroll
        for (int i = 0; i < 4; i++)
#pragma unroll
            for (int j = 0; j < 4; j++) acc[i][j] += a[i] * b[j];
    }
    float* Cp = C + (size_t)bh * NNX * NNX;
#pragma unroll
    for (int i = 0; i < 4; i++)
#pragma unroll
        for (int j = 0; j < 4; j++)
            Cp[(size_t)(m0 + tm * 4 + i) * NNX + n0 + tn * 4 + j] = acc[i][j];
}

// ======================= fused 18->6 channel mix + softmax =======================
__global__ __launch_bounds__(512)
void mix_softmax(const float* __restrict__ scale_p, const float* __restrict__ rs_p,
                 const float* __restrict__ gs_p, const float* __restrict__ conv_w,
                 const float* __restrict__ conv_b, float* __restrict__ attn_out)
{
    int bn = blockIdx.x;
    int b = bn >> 9, n = bn & 511;
    int t = threadIdx.x;               // m index
    __shared__ float cw[108], cb[6], sq4[6], sca[3];
    __shared__ float red2[16];
    if (t < 108) cw[t] = conv_w[t];
    if (t < 6) { cb[t] = conv_b[t]; sq4[t] = g_qn4[(b * 6 + t) * 512 + n]; }
    if (t == 120) sca[0] = scale_p[0];
    if (t == 121) sca[1] = rs_p[0];
    if (t == 122) sca[2] = gs_p[0];
    __syncthreads();

    float mix[6];
#pragma unroll
    for (int o = 0; o < 6; o++) mix[o] = cb[o];
#pragma unroll
    for (int h = 0; h < 6; h++) {
        size_t base = ((size_t)(b * 6 + h) * 512 + n) * 512 + t;
        float qk = g_qk[base];
        float dd = g_dd[base];
        float kn4 = g_kn4[(b * 6 + h) * 512 + t];
        float eu = qk * sca[0];
        float ri = sqrtf(fmaxf(sq4[h] + kn4 - 2.0f * qk * qk, 0.0f)) * sca[1];
        float gr = dd * dd * sca[2];
#pragma unroll
        for (int o = 0; o < 6; o++)
            mix[o] += cw[o * 18 + h] * eu + cw[o * 18 + 6 + h] * ri + cw[o * 18 + 12 + h] * gr;
    }

    int lane = t & 31, wid = t >> 5;
    for (int o = 0; o < 6; o++) {
        float v = mix[o];
#pragma unroll
        for (int of = 16; of; of >>= 1) v = fmaxf(v, __shfl_xor_sync(0xffffffffu, v, of));
        if (lane == 0) red2[wid] = v;
        __syncthreads();
        if (t < 32) {
            float x = (t < 16) ? red2[t] : -3.4e38f;
#pragma unroll
            for (int of = 8; of; of >>= 1) x = fmaxf(x, __shfl_xor_sync(0xffffffffu, x, of));
            if (t == 0) red2[0] = x;
        }
        __syncthreads();
        float mx = red2[0];
        __syncthreads();
        float e = expf(mix[o] - mx);
        float s = e;
#pragma unroll
        for (int of = 16; of; of >>= 1) s += __shfl_xor_sync(0xffffffffu, s, of);
        if (lane == 0) red2[wid] = s;
        __syncthreads();
        if (t < 32) {
            float x = (t < 16) ? red2[t] : 0.f;
#pragma unroll
            for (int of = 8; of; of >>= 1) x += __shfl_xor_sync(0xffffffffu, x, of);
            if (t == 0) red2[0] = x;
        }
        __syncthreads();
        float r = e / red2[0];
        attn_out[((size_t)(b * 6 + o) * 512 + n) * 512 + t] = r;
        __syncthreads();
    }
}

// ======================= batched attn @ V : C[bh][512,64], scattered to [B,N,C] =======================
__global__ __launch_bounds__(256)
void bgemm_av(const float* __restrict__ attn)
{
    __shared__ float As[32 * 68];
    __shared__ float Vs[32 * 68];
    int bh = blockIdx.y;
    int m0 = blockIdx.x * 64;
    int b = bh / 6, h = bh - b * 6;
    int t = threadIdx.x, tm = t >> 4, tn = t & 15;
    const float* Ap = attn + (size_t)bh * NNX * NNX;
    const float* Vp = g_v + (size_t)bh * NNX * HDX;
    float acc[4][4];
#pragma unroll
    for (int i = 0; i < 4; i++)
#pragma unroll
        for (int j = 0; j < 4; j++) acc[i][j] = 0.f;

    for (int kt = 0; kt < NNX; kt += 32) {
#pragma unroll
        for (int u = 0; u < 2; u++) {
            int p = t + u * 256;
            int r = p >> 3, cg = p & 7;
            float4 av = *(const float4*)(Ap + (size_t)(m0 + r) * NNX + kt + cg * 4);
            As[(cg * 4 + 0) * 68 + r] = av.x;
            As[(cg * 4 + 1) * 68 + r] = av.y;
            As[(cg * 4 + 2) * 68 + r] = av.z;
            As[(cg * 4 + 3) * 68 + r] = av.w;
            int r2 = p >> 4, cg2 = p & 15;
            float4 vv = *(const float4*)(Vp + (size_t)(kt + r2) * 64 + cg2 * 4);
            Vs[r2 * 68 + cg2 * 4 + 0] = vv.x;
            Vs[r2 * 68 + cg2 * 4 + 1] = vv.y;
            Vs[r2 * 68 + cg2 * 4 + 2] = vv.z;
            Vs[r2 * 68 + cg2 * 4 + 3] = vv.w;
        }
        __syncthreads();
#pragma unroll 8
        for (int k = 0; k < 32; k++) {
            float a[4], bv[4];
#pragma unroll
            for (int i = 0; i < 4; i++) a[i] = As[k * 68 + tm * 4 + i];
#pragma unroll
            for (int j = 0; j < 4; j++) bv[j] = Vs[k * 68 + tn * 4 + j];
#pragma unroll
            for (int i = 0; i < 4; i++)
#pragma unroll
                for (int j = 0; j < 4; j++) acc[i][j] += a[i] * bv[j];
        }
        __syncthreads();
    }
#pragma unroll
    for (int i = 0; i < 4; i++)
#pragma unroll
        for (int j = 0; j < 4; j++) {
            int m = m0 + tm * 4 + i;
            int nn = tn * 4 + j;
            g_attnv[(size_t)(b * 512 + m) * CCX + h * 64 + nn] = acc[i][j];
        }
}

// ======================= launch =======================
extern "C" void kernel_launch(void* const* d_in, const int* in_sizes, int n_in,
                              void* d_out, int out_size)
{
    const float* src    = (const float*)d_in[0];
    const float* pre_w  = (const float*)d_in[1];
    const float* pre_b  = (const float*)d_in[2];
    const float* qkv_w  = (const float*)d_in[3];
    const float* qkv_b  = (const float*)d_in[4];
    const float* scale  = (const float*)d_in[5];
    const float* riem   = (const float*)d_in[6];
    const float* grass  = (const float*)d_in[7];
    const float* conv_w = (const float*)d_in[8];
    const float* conv_b = (const float*)d_in[9];
    const float* proj_w = (const float*)d_in[10];
    const float* proj_b = (const float*)d_in[11];
    const float* n1_w   = (const float*)d_in[12];
    const float* n1_b   = (const float*)d_in[13];
    const float* l1_w   = (const float*)d_in[14];
    const float* l1_b   = (const float*)d_in[15];
    const float* l2_w   = (const float*)d_in[16];
    const float* l2_b   = (const float*)d_in[17];
    float* out = (float*)d_out;

    void *p_x, *p_q, *p_k, *p_qgr, *p_kgr, *p_qk, *p_dd, *p_attnv, *p_src1, *p_hff;
    cudaGetSymbolAddress(&p_x, g_x);
    cudaGetSymbolAddress(&p_q, g_q);
    cudaGetSymbolAddress(&p_k, g_k);
    cudaGetSymbolAddress(&p_qgr, g_qgr);
    cudaGetSymbolAddress(&p_kgr, g_kgr);
    cudaGetSymbolAddress(&p_qk, g_qk);
    cudaGetSymbolAddress(&p_dd, g_dd);
    cudaGetSymbolAddress(&p_attnv, g_attnv);
    cudaGetSymbolAddress(&p_src1, g_src1);
    cudaGetSymbolAddress(&p_hff, g_hff);

    // 1. pre-LN
    ln_kernel<<<MTOK, 128>>>(src, pre_w, pre_b, (float*)p_x);
    // 2. QKV projection (tf32 mma), scattered into per-head q/k/v
    mmgemm_abt<EPI_QKV><<<dim3(FFD / 128, MTOK / 128), 256>>>(
        (const float*)p_x, qkv_w, qkv_b, nullptr, nullptr, MTOK, FFD, CCX);
    // 3. row norms^4
    norms_kernel<<<(BHX * NNX + 255) / 256, 256>>>();
    // 4. register-resident Householder QR, q and k in one launch (192 blocks)
    qr_kernel2<<<2 * BHX, 512>>>((const float*)p_q, (float*)p_qgr,
                                 (const float*)p_k, (float*)p_kgr);
    // 5. score GEMMs (fp32)
    bgemm_nt<<<dim3(8, 8, BHX), 256>>>((const float*)p_q, (const float*)p_k, (float*)p_qk);
    bgemm_nt<<<dim3(8, 8, BHX), 256>>>((const float*)p_qgr, (const float*)p_kgr, (float*)p_dd);
    // 6. fused channel-mix + softmax -> attn output region of d_out
    float* attn_out = out + OUT_ATTN_OFF;
    mix_softmax<<<MTOK, 512>>>(scale, riem, grass, conv_w, conv_b, attn_out);
    // 7. attn @ V -> [B,N,C] layout (fp32)
    bgemm_av<<<dim3(8, BHX), 256>>>(attn_out);
    // 8. output projection + residual with original src (tf32 mma)
    mmgemm_abt<EPI_RESID><<<dim3(CCX / 128, MTOK / 128), 256>>>(
        (const float*)p_attnv, proj_w, proj_b, src, (float*)p_src1, MTOK, CCX, CCX);
    // 9. norm1
    ln_kernel<<<MTOK, 128>>>((const float*)p_src1, n1_w, n1_b, (float*)p_x);
    // 10. FF lin1 + exact GELU (tf32 mma)
    mmgemm_abt<EPI_GELU><<<dim3(FFD / 128, MTOK / 128), 256>>>(
        (const float*)p_x, l1_w, l1_b, nullptr, (float*)p_hff, MTOK, FFD, CCX);
    // 11. FF lin2 + residual -> src part of d_out (tf32 mma)
    mmgemm_abt<EPI_RESID><<<dim3(CCX / 128, MTOK / 128), 256>>>(
        (const float*)p_hff, l2_w, l2_b, (const float*)p_x, out, MTOK, CCX, FFD);

    (void)in_sizes; (void)n_in; (void)out_size;
}